// round 7
// baseline (speedup 1.0000x reference)
#include <cuda_runtime.h>
#include <cstdint>

#define DIM    128
#define TM     64
#define SAT    68     // A^T row stride (mult of 4 -> 16B-aligned LDS.128)
#define NNODES 50000

// Scratch (no cudaMalloc allowed)
__device__ __align__(16) float g_h[(size_t)NNODES * DIM];
__device__ __align__(16) float g_n[(size_t)NNODES * DIM];
__device__ __align__(16) float g_wt[2][DIM * DIM];   // W^T: [k][col]

#define FMA_F32X2(d, a, b) \
    asm("fma.rn.f32x2 %0, %1, %2, %0;" : "+l"(d) : "l"(a), "l"(b))
#define PACK_DUP_F32X2(d, x) \
    asm("mov.b64 %0, {%1, %1};" : "=l"(d) : "f"(x))
#define UNPACK_F32X2(lo, hi, v) \
    asm("mov.b64 {%0, %1}, %2;" : "=f"(lo), "=f"(hi) : "l"(v))

// One-shot: transpose both weight matrices into global W^T buffers.
__global__ __launch_bounds__(256) void transpose_w_kernel(
    const float* __restrict__ W0, const float* __restrict__ W1)
{
    int i = blockIdx.x * 256 + threadIdx.x;   // i = k*128 + c, 16384 total
    int k = i >> 7, c = i & 127;
    g_wt[0][i] = W0[c * DIM + k];
    g_wt[1][i] = W1[c * DIM + k];
}

// C[M,128] = relu(A[M,128] @ W^T + bias); optionally n_init = 1 + eps*C
// W^T streamed from global (L1-resident, shared across CTAs); A tile in smem.
__global__ __launch_bounds__(256, 4) void gemm_relu_kernel(
    const float* __restrict__ A, const float* __restrict__ Wt,
    const float* __restrict__ bias, float* __restrict__ out,
    float* __restrict__ n_init, const float* __restrict__ eps, int M)
{
    __shared__ float AsT[DIM * SAT];   // 34,816 B -> 4 CTAs/SM

    const int tid  = threadIdx.x;
    const int row0 = blockIdx.x * TM;

    // A tile transpose load: LDG coalesced; STS 4-way conflict (one-time)
    for (int i = tid; i < TM * DIM; i += 256) {
        int r = i >> 7, c = i & 127;
        int gr = row0 + r;
        AsT[c * SAT + r] = (gr < M) ? A[(size_t)gr * DIM + c] : 0.0f;
    }
    __syncthreads();

    // Micro-tile: 4 rows x 8 cols per thread.
    const int tg = tid >> 4;       // 0..15
    const int tc = tid & 15;       // 0..15
    const int rr = tg * 4;
    const int cc = tc * 4;

    const float* pW = Wt + cc;     // + k*DIM

    unsigned long long acc[4][2][2];   // [row][half][pair] as f32x2
#pragma unroll
    for (int i = 0; i < 4; ++i)
#pragma unroll
        for (int j = 0; j < 2; ++j) { acc[i][j][0] = 0ULL; acc[i][j][1] = 0ULL; }

    // Prefetch W row k+1 (global/L1, ~39cyc) one iteration ahead; A via LDS
    // in-iteration (29cyc hidden by 8 warps/SMSP at 4 CTAs).
    ulonglong2 w0_nx = *reinterpret_cast<const ulonglong2*>(pW);
    ulonglong2 w1_nx = *reinterpret_cast<const ulonglong2*>(pW + 64);

#pragma unroll 4
    for (int k = 0; k < DIM; ++k) {
        ulonglong2 w0 = w0_nx;
        ulonglong2 w1 = w1_nx;

        int kn = (k + 1 < DIM) ? (k + 1) : k;
        w0_nx = *reinterpret_cast<const ulonglong2*>(pW + kn * DIM);
        w1_nx = *reinterpret_cast<const ulonglong2*>(pW + kn * DIM + 64);

        float4 a = *reinterpret_cast<const float4*>(&AsT[k * SAT + rr]);
        unsigned long long aP[4];
        PACK_DUP_F32X2(aP[0], a.x);
        PACK_DUP_F32X2(aP[1], a.y);
        PACK_DUP_F32X2(aP[2], a.z);
        PACK_DUP_F32X2(aP[3], a.w);

#pragma unroll
        for (int i = 0; i < 4; ++i) {
            FMA_F32X2(acc[i][0][0], aP[i], w0.x);
            FMA_F32X2(acc[i][0][1], aP[i], w0.y);
            FMA_F32X2(acc[i][1][0], aP[i], w1.x);
            FMA_F32X2(acc[i][1][1], aP[i], w1.y);
        }
    }

    const float e = (n_init != nullptr) ? eps[0] : 0.0f;
#pragma unroll
    for (int i = 0; i < 4; ++i) {
        int gr = row0 + rr + i;
        if (gr >= M) continue;
#pragma unroll
        for (int j = 0; j < 2; ++j) {
            int c = cc + 64 * j;
            float4 b = *reinterpret_cast<const float4*>(&bias[c]);
            float v0, v1, v2, v3;
            UNPACK_F32X2(v0, v1, acc[i][j][0]);
            UNPACK_F32X2(v2, v3, acc[i][j][1]);
            v0 = fmaxf(v0 + b.x, 0.0f);
            v1 = fmaxf(v1 + b.y, 0.0f);
            v2 = fmaxf(v2 + b.z, 0.0f);
            v3 = fmaxf(v3 + b.w, 0.0f);
            *reinterpret_cast<float4*>(&out[(size_t)gr * DIM + c])
                = make_float4(v0, v1, v2, v3);
            if (n_init)
                *reinterpret_cast<float4*>(&n_init[(size_t)gr * DIM + c])
                    = make_float4(1.0f + e * v0, 1.0f + e * v1,
                                  1.0f + e * v2, 1.0f + e * v3);
        }
    }
}

// One warp per edge: gather h[src] (float4 per lane), atomicAdd(float4) to n[dst]
// src/dst are int32 (JAX x64 disabled).
__global__ __launch_bounds__(256) void scatter_kernel(
    const float* __restrict__ h, const int* __restrict__ src,
    const int* __restrict__ dst, float* __restrict__ nacc, int E)
{
    int gid  = blockIdx.x * blockDim.x + threadIdx.x;
    int e    = gid >> 5;
    int lane = gid & 31;
    if (e >= E) return;

    int s = src[e];
    int d = dst[e];

    float4 v = reinterpret_cast<const float4*>(h + (size_t)s * DIM)[lane];
    atomicAdd(reinterpret_cast<float4*>(nacc + (size_t)d * DIM) + lane, v);
}

extern "C" void kernel_launch(void* const* d_in, const int* in_sizes, int n_in,
                              void* d_out, int out_size)
{
    const float* feats = (const float*)d_in[0];
    const int*   src   = (const int*)d_in[1];
    const int*   dst   = (const int*)d_in[2];
    const float* W_f   = (const float*)d_in[3];
    const float* b_f   = (const float*)d_in[4];
    const float* W_phy = (const float*)d_in[5];
    const float* b_phy = (const float*)d_in[6];
    const float* eps   = (const float*)d_in[7];
    float*       out   = (float*)d_out;

    const int M = in_sizes[0] / DIM;    // 50000
    const int E = in_sizes[1];          // 625000

    float *h_ptr, *n_ptr, *wt_ptr;
    cudaGetSymbolAddress((void**)&h_ptr, g_h);
    cudaGetSymbolAddress((void**)&n_ptr, g_n);
    cudaGetSymbolAddress((void**)&wt_ptr, g_wt);

    const int gblocks = (M + TM - 1) / TM;   // 782

    // One-shot weight transposes (both matrices)
    transpose_w_kernel<<<(DIM * DIM) / 256, 256>>>(W_f, W_phy);

    // h = relu(feats W_f^T + b_f); n = 1 + eps*h
    gemm_relu_kernel<<<gblocks, 256>>>(feats, wt_ptr, b_f, h_ptr, n_ptr, eps, M);

    // n += sum_{edges} h[src] at dst
    long long total_threads = (long long)E * 32;
    int sblocks = (int)((total_threads + 255) / 256);
    scatter_kernel<<<sblocks, 256>>>(h_ptr, src, dst, n_ptr, E);

    // out = relu(n W_phy^T + b_phy)
    gemm_relu_kernel<<<gblocks, 256>>>(n_ptr, wt_ptr + DIM * DIM, b_phy,
                                       out, nullptr, nullptr, M);
}

// round 8
// speedup vs baseline: 1.2701x; 1.2701x over previous
#include <cuda_runtime.h>
#include <cstdint>

#define DIM    128
#define TM     64
#define SAT    68     // A^T row stride (mult of 4 -> 16B-aligned LDS.128; 4-way STS conflict one-time)
#define NNODES 50000

// Scratch (no cudaMalloc allowed)
__device__ __align__(16) float g_h[(size_t)NNODES * DIM];
__device__ __align__(16) float g_n[(size_t)NNODES * DIM];
__device__ __align__(16) float g_wt[2][DIM * DIM];   // W^T: [k][col]

#define FMA_F32X2(d, a, b) \
    asm("fma.rn.f32x2 %0, %1, %2, %0;" : "+l"(d) : "l"(a), "l"(b))
#define PACK_DUP_F32X2(d, x) \
    asm("mov.b64 %0, {%1, %1};" : "=l"(d) : "f"(x))
#define UNPACK_F32X2(lo, hi, v) \
    asm("mov.b64 {%0, %1}, %2;" : "=f"(lo), "=f"(hi) : "l"(v))

// One-shot: transpose both weight matrices into global W^T buffers.
// Writes coalesced; reads strided (W is 64KB -> L2-resident immediately).
__global__ __launch_bounds__(256) void transpose_w_kernel(
    const float* __restrict__ W0, const float* __restrict__ W1)
{
    int i = blockIdx.x * 256 + threadIdx.x;   // i = k*128 + c
    int k = i >> 7, c = i & 127;
    g_wt[0][i] = W0[c * DIM + k];
    g_wt[1][i] = W1[c * DIM + k];
}

// C[M,128] = relu(A[M,128] @ W^T + bias); optionally n_init = 1 + eps*C
// Micro-tile 8 rows x 4 cols/thread; acc packed as f32x2 over row-pairs.
__global__ __launch_bounds__(256, 2) void gemm_relu_kernel(
    const float* __restrict__ A, const float* __restrict__ Wt,
    const float* __restrict__ bias, float* __restrict__ out,
    float* __restrict__ n_init, const float* __restrict__ eps, int M)
{
    extern __shared__ float smem[];
    float* Ws  = smem;              // W^T [k=128][128], linear copy of g_wt slice
    float* AsT = smem + DIM * DIM;  // A^T tile [k=128][SAT]

    const int tid  = threadIdx.x;
    const int row0 = blockIdx.x * TM;

    // W^T copy: linear float4, conflict-free, coalesced. 16384 floats.
    {
        const float4* srcW = reinterpret_cast<const float4*>(Wt);
        float4* dstW = reinterpret_cast<float4*>(Ws);
#pragma unroll
        for (int i = 0; i < (DIM * DIM / 4) / 256; ++i)
            dstW[i * 256 + tid] = srcW[i * 256 + tid];
    }
    // A tile transpose: LDG float4 coalesced; 4 scalar STS (4-way conflict, one-time).
#pragma unroll
    for (int it = 0; it < (TM * DIM / 4) / 256; ++it) {
        int idx = it * 256 + tid;
        int r = idx >> 5;             // 0..63
        int c = (idx & 31) * 4;       // 0,4,..124
        int gr = row0 + r;
        float4 v = (gr < M) ? *reinterpret_cast<const float4*>(A + (size_t)gr * DIM + c)
                            : make_float4(0.f, 0.f, 0.f, 0.f);
        AsT[(c + 0) * SAT + r] = v.x;
        AsT[(c + 1) * SAT + r] = v.y;
        AsT[(c + 2) * SAT + r] = v.z;
        AsT[(c + 3) * SAT + r] = v.w;
    }
    __syncthreads();

    // Thread layout: warp tg owns rows rr..rr+7 (whole warp same rows -> broadcast LDS);
    // lane tc owns cols cc..cc+3.
    const int tg = tid >> 5;       // 0..7
    const int tc = tid & 31;       // 0..31
    const int rr = tg * 8;
    const int cc = tc * 4;

    unsigned long long acc[4][4];  // [rowpair][col], f32x2 = (row even, row odd)
#pragma unroll
    for (int i = 0; i < 4; ++i)
#pragma unroll
        for (int j = 0; j < 4; ++j) acc[i][j] = 0ULL;

#pragma unroll 8
    for (int k = 0; k < DIM; ++k) {
        // a: 8 rows = 4 natural f32x2 pairs, 2 broadcast LDS.128 (1 wf each)
        ulonglong2 a01 = *reinterpret_cast<const ulonglong2*>(&AsT[k * SAT + rr]);
        ulonglong2 a23 = *reinterpret_cast<const ulonglong2*>(&AsT[k * SAT + rr + 4]);
        // w: 4 cols, 1 LDS.128 (4 wf), duplicated into f32x2
        float4 w = *reinterpret_cast<const float4*>(&Ws[k * DIM + cc]);
        unsigned long long wD[4];
        PACK_DUP_F32X2(wD[0], w.x);
        PACK_DUP_F32X2(wD[1], w.y);
        PACK_DUP_F32X2(wD[2], w.z);
        PACK_DUP_F32X2(wD[3], w.w);

#pragma unroll
        for (int j = 0; j < 4; ++j) {
            FMA_F32X2(acc[0][j], a01.x, wD[j]);
            FMA_F32X2(acc[1][j], a01.y, wD[j]);
            FMA_F32X2(acc[2][j], a23.x, wD[j]);
            FMA_F32X2(acc[3][j], a23.y, wD[j]);
        }
    }

    const float e = (n_init != nullptr) ? eps[0] : 0.0f;
    const float4 b4 = *reinterpret_cast<const float4*>(&bias[cc]);
#pragma unroll
    for (int rp = 0; rp < 4; ++rp) {
        float v0[4], v1[4];   // row rr+2rp, row rr+2rp+1
#pragma unroll
        for (int j = 0; j < 4; ++j) UNPACK_F32X2(v0[j], v1[j], acc[rp][j]);

        int gr0 = row0 + rr + 2 * rp;
#pragma unroll
        for (int half = 0; half < 2; ++half) {
            int gr = gr0 + half;
            if (gr >= M) continue;
            const float* vv = half ? v1 : v0;
            float o0 = fmaxf(vv[0] + b4.x, 0.0f);
            float o1 = fmaxf(vv[1] + b4.y, 0.0f);
            float o2 = fmaxf(vv[2] + b4.z, 0.0f);
            float o3 = fmaxf(vv[3] + b4.w, 0.0f);
            *reinterpret_cast<float4*>(&out[(size_t)gr * DIM + cc])
                = make_float4(o0, o1, o2, o3);
            if (n_init)
                *reinterpret_cast<float4*>(&n_init[(size_t)gr * DIM + cc])
                    = make_float4(1.0f + e * o0, 1.0f + e * o1,
                                  1.0f + e * o2, 1.0f + e * o3);
        }
    }
}

// One warp per edge: gather h[src] (float4 per lane), atomicAdd(float4) to n[dst]
// src/dst are int32 (JAX x64 disabled).
__global__ __launch_bounds__(256) void scatter_kernel(
    const float* __restrict__ h, const int* __restrict__ src,
    const int* __restrict__ dst, float* __restrict__ nacc, int E)
{
    int gid  = blockIdx.x * blockDim.x + threadIdx.x;
    int e    = gid >> 5;
    int lane = gid & 31;
    if (e >= E) return;

    int s = src[e];
    int d = dst[e];

    float4 v = reinterpret_cast<const float4*>(h + (size_t)s * DIM)[lane];
    atomicAdd(reinterpret_cast<float4*>(nacc + (size_t)d * DIM) + lane, v);
}

extern "C" void kernel_launch(void* const* d_in, const int* in_sizes, int n_in,
                              void* d_out, int out_size)
{
    const float* feats = (const float*)d_in[0];
    const int*   src   = (const int*)d_in[1];
    const int*   dst   = (const int*)d_in[2];
    const float* W_f   = (const float*)d_in[3];
    const float* b_f   = (const float*)d_in[4];
    const float* W_phy = (const float*)d_in[5];
    const float* b_phy = (const float*)d_in[6];
    const float* eps   = (const float*)d_in[7];
    float*       out   = (float*)d_out;

    const int M = in_sizes[0] / DIM;    // 50000
    const int E = in_sizes[1];          // 625000

    float *h_ptr, *n_ptr, *wt_ptr;
    cudaGetSymbolAddress((void**)&h_ptr, g_h);
    cudaGetSymbolAddress((void**)&n_ptr, g_n);
    cudaGetSymbolAddress((void**)&wt_ptr, g_wt);

    const size_t smem = (size_t)(DIM * DIM + DIM * SAT) * sizeof(float);  // 100,352 B
    cudaFuncSetAttribute(gemm_relu_kernel,
                         cudaFuncAttributeMaxDynamicSharedMemorySize, (int)smem);

    const int gblocks = (M + TM - 1) / TM;   // 782

    // One-shot weight transposes (both matrices)
    transpose_w_kernel<<<(DIM * DIM) / 256, 256>>>(W_f, W_phy);

    // h = relu(feats W_f^T + b_f); n = 1 + eps*h
    gemm_relu_kernel<<<gblocks, 256, smem>>>(feats, wt_ptr, b_f, h_ptr, n_ptr, eps, M);

    // n += sum_{edges} h[src] at dst
    long long total_threads = (long long)E * 32;
    int sblocks = (int)((total_threads + 255) / 256);
    scatter_kernel<<<sblocks, 256>>>(h_ptr, src, dst, n_ptr, E);

    // out = relu(n W_phy^T + b_phy)
    gemm_relu_kernel<<<gblocks, 256, smem>>>(n_ptr, wt_ptr + DIM * DIM, b_phy,
                                             out, nullptr, nullptr, M);
}

// round 9
// speedup vs baseline: 1.2952x; 1.0198x over previous
#include <cuda_runtime.h>
#include <cstdint>

#define DIM    128
#define TM     64
#define SAT    68     // A^T row stride (mult of 4 -> 16B-aligned LDS.128)
#define NNODES 50000
#define PGRID  296    // persistent grid: 2 CTAs x 148 SMs

// Scratch (no cudaMalloc allowed)
__device__ __align__(16) float g_h[(size_t)NNODES * DIM];
__device__ __align__(16) float g_n[(size_t)NNODES * DIM];
__device__ __align__(16) float g_wt[2][DIM * DIM];   // W^T: [k][col]

#define FMA_F32X2(d, a, b) \
    asm("fma.rn.f32x2 %0, %1, %2, %0;" : "+l"(d) : "l"(a), "l"(b))
#define PACK_DUP_F32X2(d, x) \
    asm("mov.b64 %0, {%1, %1};" : "=l"(d) : "f"(x))
#define UNPACK_F32X2(lo, hi, v) \
    asm("mov.b64 {%0, %1}, %2;" : "=f"(lo), "=f"(hi) : "l"(v))

// One-shot: transpose both weight matrices into global W^T buffers.
__global__ __launch_bounds__(256) void transpose_w_kernel(
    const float* __restrict__ W0, const float* __restrict__ W1)
{
    int i = blockIdx.x * 256 + threadIdx.x;   // i = k*128 + c
    int k = i >> 7, c = i & 127;
    g_wt[0][i] = W0[c * DIM + k];
    g_wt[1][i] = W1[c * DIM + k];
}

// Persistent GEMM: W^T loaded into smem ONCE per CTA, then grid-stride over
// A-tiles. C[M,128] = relu(A @ W^T + bias); optionally n_init = 1 + eps*C.
__global__ __launch_bounds__(256, 2) void gemm_persist_kernel(
    const float* __restrict__ A, const float* __restrict__ Wt,
    const float* __restrict__ bias, float* __restrict__ out,
    float* __restrict__ n_init, const float* __restrict__ eps,
    int M, int ntiles)
{
    extern __shared__ float smem[];
    float* Ws  = smem;              // W^T [k=128][128]
    float* AsT = smem + DIM * DIM;  // A^T tile [k=128][SAT]

    const int tid = threadIdx.x;

    // W^T copy once: linear float4, conflict-free, coalesced.
    {
        const float4* srcW = reinterpret_cast<const float4*>(Wt);
        float4* dstW = reinterpret_cast<float4*>(Ws);
#pragma unroll
        for (int i = 0; i < (DIM * DIM / 4) / 256; ++i)
            dstW[i * 256 + tid] = srcW[i * 256 + tid];
    }

    // Thread layout: warp tg owns rows rr..rr+7 (broadcast LDS); lane owns 4 cols.
    const int tg = tid >> 5;       // 0..7
    const int tc = tid & 31;       // 0..31
    const int rr = tg * 8;
    const int cc = tc * 4;

    const float e = (n_init != nullptr) ? eps[0] : 0.0f;
    const float4 b4 = *reinterpret_cast<const float4*>(&bias[cc]);

    for (int t = blockIdx.x; t < ntiles; t += gridDim.x) {
        const int row0 = t * TM;

        __syncthreads();   // prior mainloop done with AsT (and W copy on iter 0)

        // A tile transpose: LDG float4 coalesced; 4 scalar STS (4-way, one-time).
#pragma unroll
        for (int it = 0; it < (TM * DIM / 4) / 256; ++it) {
            int idx = it * 256 + tid;
            int r = idx >> 5;             // 0..63
            int c = (idx & 31) * 4;       // 0,4,..,124
            int gr = row0 + r;
            float4 v = (gr < M)
                ? *reinterpret_cast<const float4*>(A + (size_t)gr * DIM + c)
                : make_float4(0.f, 0.f, 0.f, 0.f);
            AsT[(c + 0) * SAT + r] = v.x;
            AsT[(c + 1) * SAT + r] = v.y;
            AsT[(c + 2) * SAT + r] = v.z;
            AsT[(c + 3) * SAT + r] = v.w;
        }
        __syncthreads();

        unsigned long long acc[4][4];  // [rowpair][col], f32x2 = (even,odd) rows
#pragma unroll
        for (int i = 0; i < 4; ++i)
#pragma unroll
            for (int j = 0; j < 4; ++j) acc[i][j] = 0ULL;

#pragma unroll 8
        for (int k = 0; k < DIM; ++k) {
            // a: 8 rows = 4 natural f32x2 pairs, 2 broadcast LDS.128
            ulonglong2 a01 = *reinterpret_cast<const ulonglong2*>(&AsT[k * SAT + rr]);
            ulonglong2 a23 = *reinterpret_cast<const ulonglong2*>(&AsT[k * SAT + rr + 4]);
            // w: 4 cols, 1 LDS.128, duplicated into f32x2
            float4 w = *reinterpret_cast<const float4*>(&Ws[k * DIM + cc]);
            unsigned long long wD[4];
            PACK_DUP_F32X2(wD[0], w.x);
            PACK_DUP_F32X2(wD[1], w.y);
            PACK_DUP_F32X2(wD[2], w.z);
            PACK_DUP_F32X2(wD[3], w.w);

#pragma unroll
            for (int j = 0; j < 4; ++j) {
                FMA_F32X2(acc[0][j], a01.x, wD[j]);
                FMA_F32X2(acc[1][j], a01.y, wD[j]);
                FMA_F32X2(acc[2][j], a23.x, wD[j]);
                FMA_F32X2(acc[3][j], a23.y, wD[j]);
            }
        }

#pragma unroll
        for (int rp = 0; rp < 4; ++rp) {
            float v0[4], v1[4];
#pragma unroll
            for (int j = 0; j < 4; ++j) UNPACK_F32X2(v0[j], v1[j], acc[rp][j]);

            int gr0 = row0 + rr + 2 * rp;
#pragma unroll
            for (int half = 0; half < 2; ++half) {
                int gr = gr0 + half;
                if (gr >= M) continue;
                const float* vv = half ? v1 : v0;
                float o0 = fmaxf(vv[0] + b4.x, 0.0f);
                float o1 = fmaxf(vv[1] + b4.y, 0.0f);
                float o2 = fmaxf(vv[2] + b4.z, 0.0f);
                float o3 = fmaxf(vv[3] + b4.w, 0.0f);
                *reinterpret_cast<float4*>(&out[(size_t)gr * DIM + cc])
                    = make_float4(o0, o1, o2, o3);
                if (n_init)
                    *reinterpret_cast<float4*>(&n_init[(size_t)gr * DIM + cc])
                        = make_float4(1.0f + e * o0, 1.0f + e * o1,
                                      1.0f + e * o2, 1.0f + e * o3);
            }
        }
    }
}

// One warp per edge: gather h[src] (float4 per lane), atomicAdd(float4) to n[dst]
// src/dst are int32 (JAX x64 disabled).
__global__ __launch_bounds__(256) void scatter_kernel(
    const float* __restrict__ h, const int* __restrict__ src,
    const int* __restrict__ dst, float* __restrict__ nacc, int E)
{
    int gid  = blockIdx.x * blockDim.x + threadIdx.x;
    int e    = gid >> 5;
    int lane = gid & 31;
    if (e >= E) return;

    int s = src[e];
    int d = dst[e];

    float4 v = reinterpret_cast<const float4*>(h + (size_t)s * DIM)[lane];
    atomicAdd(reinterpret_cast<float4*>(nacc + (size_t)d * DIM) + lane, v);
}

extern "C" void kernel_launch(void* const* d_in, const int* in_sizes, int n_in,
                              void* d_out, int out_size)
{
    const float* feats = (const float*)d_in[0];
    const int*   src   = (const int*)d_in[1];
    const int*   dst   = (const int*)d_in[2];
    const float* W_f   = (const float*)d_in[3];
    const float* b_f   = (const float*)d_in[4];
    const float* W_phy = (const float*)d_in[5];
    const float* b_phy = (const float*)d_in[6];
    const float* eps   = (const float*)d_in[7];
    float*       out   = (float*)d_out;

    const int M = in_sizes[0] / DIM;    // 50000
    const int E = in_sizes[1];          // 625000

    float *h_ptr, *n_ptr, *wt_ptr;
    cudaGetSymbolAddress((void**)&h_ptr, g_h);
    cudaGetSymbolAddress((void**)&n_ptr, g_n);
    cudaGetSymbolAddress((void**)&wt_ptr, g_wt);

    const size_t smem = (size_t)(DIM * DIM + DIM * SAT) * sizeof(float);  // 100,352 B
    cudaFuncSetAttribute(gemm_persist_kernel,
                         cudaFuncAttributeMaxDynamicSharedMemorySize, (int)smem);

    const int ntiles = (M + TM - 1) / TM;   // 782

    // One-shot weight transposes (both matrices)
    transpose_w_kernel<<<(DIM * DIM) / 256, 256>>>(W_f, W_phy);

    // h = relu(feats W_f^T + b_f); n = 1 + eps*h
    gemm_persist_kernel<<<PGRID, 256, smem>>>(feats, wt_ptr, b_f, h_ptr,
                                              n_ptr, eps, M, ntiles);

    // n += sum_{edges} h[src] at dst
    long long total_threads = (long long)E * 32;
    int sblocks = (int)((total_threads + 255) / 256);
    scatter_kernel<<<sblocks, 256>>>(h_ptr, src, dst, n_ptr, E);

    // out = relu(n W_phy^T + b_phy)
    gemm_persist_kernel<<<PGRID, 256, smem>>>(n_ptr, wt_ptr + DIM * DIM, b_phy,
                                              out, nullptr, nullptr, M, ntiles);
}